// round 2
// baseline (speedup 1.0000x reference)
#include <cuda_runtime.h>
#include <cstdint>

// Head attention: B=16384, T=64, C=64, H=64, fp32 in/out.
// out[b,t,h] = softmax_s( (x@Wq)(x@Wk)^T * C^-0.5, causal )[t,s] @ (x@Wv)[s,h]
//
// Strategy: TF32 mma.sync.m16n8k8, 2 batches per CTA iteration (8 warps),
// W cached in smem (tf32-rounded), causal tile skipping, in-fragment softmax.

#define SP 72                 // smem row stride (floats); conflict-free frags
#define MAT (64 * SP)         // one padded 64x64 matrix (floats)
#define THREADS 256
#define GRID 888              // 6 * 148 SMs; grid-stride over batch pairs

__device__ __forceinline__ uint32_t f2tf(float f) {
    uint32_t u;
    asm("cvt.rna.tf32.f32 %0, %1;" : "=r"(u) : "f"(f));
    return u;
}
__device__ __forceinline__ float f2tf_f(float f) { return __uint_as_float(f2tf(f)); }

__device__ __forceinline__ void mma_tf32(float d[4],
    uint32_t a0, uint32_t a1, uint32_t a2, uint32_t a3,
    uint32_t b0, uint32_t b1)
{
    asm volatile(
        "mma.sync.aligned.m16n8k8.row.col.f32.tf32.tf32.f32 "
        "{%0,%1,%2,%3}, {%4,%5,%6,%7}, {%8,%9}, {%0,%1,%2,%3};"
        : "+f"(d[0]), "+f"(d[1]), "+f"(d[2]), "+f"(d[3])
        : "r"(a0), "r"(a1), "r"(a2), "r"(a3), "r"(b0), "r"(b1));
}

__device__ __forceinline__ void zero_acc(float acc[8][4]) {
#pragma unroll
    for (int i = 0; i < 8; ++i)
#pragma unroll
        for (int j = 0; j < 4; ++j) acc[i][j] = 0.0f;
}

// D[m][n] += sum_k A[m][k] * B[k][n]; A base already offset to the warp's m0.
// A: [m][k] row-major stride SP.  B: [k][n] row-major stride SP.
__device__ __forceinline__ void frag_gemm(
    const float* __restrict__ A, const float* __restrict__ B,
    float acc[8][4], int g, int t, int ktmax, int ntmax)
{
#pragma unroll
    for (int kt = 0; kt < 8; ++kt) {
        if (kt > ktmax) break;
        const float* ap = A + g * SP + kt * 8 + t;
        uint32_t a0 = __float_as_uint(ap[0]);
        uint32_t a1 = __float_as_uint(ap[8 * SP]);
        uint32_t a2 = __float_as_uint(ap[4]);
        uint32_t a3 = __float_as_uint(ap[8 * SP + 4]);
        const float* bp = B + (kt * 8 + t) * SP + g;
#pragma unroll
        for (int nt = 0; nt < 8; ++nt) {
            if (nt > ntmax) break;
            uint32_t b0 = __float_as_uint(bp[nt * 8]);
            uint32_t b1 = __float_as_uint(bp[nt * 8 + 4 * SP]);
            mma_tf32(acc[nt], a0, a1, a2, a3, b0, b1);
        }
    }
}

// Store accumulator tile to smem [row][col], tf32-rounded (it will feed MMAs).
__device__ __forceinline__ void store_norm(float* __restrict__ Cs,
    const float acc[8][4], int m0, int g, int t)
{
#pragma unroll
    for (int nt = 0; nt < 8; ++nt) {
        int c = nt * 8 + 2 * t;
        *(float2*)(Cs + (m0 + g) * SP + c) =
            make_float2(f2tf_f(acc[nt][0]), f2tf_f(acc[nt][1]));
        *(float2*)(Cs + (m0 + g + 8) * SP + c) =
            make_float2(f2tf_f(acc[nt][2]), f2tf_f(acc[nt][3]));
    }
}

// Transposed store: element (r, c) -> Cs[c][r].  (k-matrix stored as [h][s])
__device__ __forceinline__ void store_trans(float* __restrict__ Cs,
    const float acc[8][4], int m0, int g, int t)
{
#pragma unroll
    for (int nt = 0; nt < 8; ++nt) {
        int c = nt * 8 + 2 * t;
        Cs[(c    ) * SP + m0 + g    ] = f2tf_f(acc[nt][0]);
        Cs[(c + 1) * SP + m0 + g    ] = f2tf_f(acc[nt][1]);
        Cs[(c    ) * SP + m0 + g + 8] = f2tf_f(acc[nt][2]);
        Cs[(c + 1) * SP + m0 + g + 8] = f2tf_f(acc[nt][3]);
    }
}

__global__ void __launch_bounds__(THREADS, 1)
head_attn_kernel(const float* __restrict__ x,
                 const float* __restrict__ Wk,
                 const float* __restrict__ Wq,
                 const float* __restrict__ Wv,
                 float* __restrict__ out,
                 int nb)
{
    extern __shared__ float sm[];
    float* wq_s = sm;               // [c][h]
    float* wk_s = sm + MAT;
    float* wv_s = sm + 2 * MAT;

    const int tid  = threadIdx.x;
    const int lane = tid & 31;
    const int warp = tid >> 5;
    const int slot = warp >> 2;     // which of the 2 batches this warp works on
    const int w4   = warp & 3;      // row-block within the batch
    const int g    = lane >> 2;     // groupID
    const int t    = lane & 3;      // threadID-in-group
    const int m0   = w4 * 16;
    const int r0   = m0 + g;

    float* xp = sm + 3 * MAT + slot * (4 * MAT);  // x tile, later reused as P
    float* qs = xp + MAT;                          // [t][h]
    float* ks = qs + MAT;                          // TRANSPOSED: [h][s]
    float* vs = ks + MAT;                          // [s][h]

    // Load weights once per CTA (tf32-rounded).
    for (int i = tid; i < 64 * 64; i += THREADS) {
        int c = i >> 6, h = i & 63;
        wq_s[c * SP + h] = f2tf_f(Wq[i]);
        wk_s[c * SP + h] = f2tf_f(Wk[i]);
        wv_s[c * SP + h] = f2tf_f(Wv[i]);
    }

    const int pairs = (nb + 1) >> 1;
    for (int p = blockIdx.x; p < pairs; p += gridDim.x) {
        __syncthreads();  // previous iteration's smem consumers done
        // Load x for both slots (tf32-rounded).
        for (int i = tid; i < 2 * 4096; i += THREADS) {
            int s = i >> 12;
            int j = i & 4095;
            int b = 2 * p + s;
            if (b < nb) {
                float* dst = sm + 3 * MAT + s * (4 * MAT);
                dst[(j >> 6) * SP + (j & 63)] = f2tf_f(x[(size_t)b * 4096 + j]);
            }
        }
        __syncthreads();

        const int b = 2 * p + slot;
        const bool valid = (b < nb);

        float acc[8][4];
        // ---- GEMM1: Q, K (transposed store), V ----
        zero_acc(acc);
        frag_gemm(xp + m0 * SP, wq_s, acc, g, t, 7, 7);
        store_norm(qs, acc, m0, g, t);

        zero_acc(acc);
        frag_gemm(xp + m0 * SP, wk_s, acc, g, t, 7, 7);
        store_trans(ks, acc, m0, g, t);

        zero_acc(acc);
        frag_gemm(xp + m0 * SP, wv_s, acc, g, t, 7, 7);
        store_norm(vs, acc, m0, g, t);
        __syncthreads();

        // ---- GEMM2: S = Q @ K^T (causal: skip n-tiles above the diagonal) ----
        const int ntmax = 2 * w4 + 1;
        zero_acc(acc);
        frag_gemm(qs + m0 * SP, ks, acc, g, t, 7, ntmax);

        // ---- softmax on accumulator fragments (rows r0 and r0+8) ----
        const float scale = 0.125f;  // C^-0.5
#pragma unroll
        for (int hh = 0; hh < 2; ++hh) {
            const int r  = r0 + hh * 8;
            const int i0 = 2 * hh;
            float mx = -1e30f;
#pragma unroll
            for (int nt = 0; nt < 8; ++nt) {
                if (nt > ntmax) break;
                int c = nt * 8 + 2 * t;
                float v0 = (c     <= r) ? acc[nt][i0    ] * scale : -1e30f;
                float v1 = (c + 1 <= r) ? acc[nt][i0 + 1] * scale : -1e30f;
                acc[nt][i0] = v0; acc[nt][i0 + 1] = v1;
                mx = fmaxf(mx, fmaxf(v0, v1));
            }
            mx = fmaxf(mx, __shfl_xor_sync(0xffffffffu, mx, 1));
            mx = fmaxf(mx, __shfl_xor_sync(0xffffffffu, mx, 2));
            float ssum = 0.0f;
#pragma unroll
            for (int nt = 0; nt < 8; ++nt) {
                if (nt > ntmax) break;
                float p0 = __expf(acc[nt][i0    ] - mx);
                float p1 = __expf(acc[nt][i0 + 1] - mx);
                acc[nt][i0] = p0; acc[nt][i0 + 1] = p1;
                ssum += p0 + p1;
            }
            ssum += __shfl_xor_sync(0xffffffffu, ssum, 1);
            ssum += __shfl_xor_sync(0xffffffffu, ssum, 2);
            const float inv = 1.0f / ssum;
#pragma unroll
            for (int nt = 0; nt < 8; ++nt) {
                if (nt > ntmax) break;
                int c = nt * 8 + 2 * t;
                *(float2*)(xp + r * SP + c) = make_float2(
                    f2tf_f(acc[nt][i0] * inv), f2tf_f(acc[nt][i0 + 1] * inv));
            }
        }
        __syncwarp();  // P rows are per-warp private; warp-local RAW only

        // ---- PV: out = P @ V (causal: skip k-steps above the diagonal) ----
        zero_acc(acc);
        frag_gemm(xp + m0 * SP, vs, acc, g, t, ntmax, 7);

        if (valid) {
            float* ob = out + (size_t)b * 4096;
#pragma unroll
            for (int nt = 0; nt < 8; ++nt) {
                int c = nt * 8 + 2 * t;
                *(float2*)(ob + r0 * 64 + c)       = make_float2(acc[nt][0], acc[nt][1]);
                *(float2*)(ob + (r0 + 8) * 64 + c) = make_float2(acc[nt][2], acc[nt][3]);
            }
        }
    }
}

extern "C" void kernel_launch(void* const* d_in, const int* in_sizes, int n_in,
                              void* d_out, int out_size)
{
    const float* x  = (const float*)d_in[0];
    const float* Wk = (const float*)d_in[1];
    const float* Wq = (const float*)d_in[2];
    const float* Wv = (const float*)d_in[3];
    float* out = (float*)d_out;
    const int nb = in_sizes[0] / (64 * 64);

    const size_t smem = (size_t)11 * MAT * sizeof(float);  // 202752 B
    cudaFuncSetAttribute(head_attn_kernel,
                         cudaFuncAttributeMaxDynamicSharedMemorySize, (int)smem);
    head_attn_kernel<<<GRID, THREADS, smem>>>(x, Wk, Wq, Wv, out, nb);
}

// round 4
// speedup vs baseline: 1.2931x; 1.2931x over previous
#include <cuda_runtime.h>
#include <cstdint>

// Head attention: B=16384, T=64, C=H=64, fp32.
// TF32 mma.sync m16n8k8. 3 batches per CTA (12 warps), Q/P kept in registers
// (shfl fragment permute), B-operands in a swizzled 64B/lane smem layout
// read with LDS.128, x with stride 68 (conflict-free LDS.32 A-frags).

#define THREADS 384
#define GRID 148
#define XS 68                  // x row stride (floats)
#define XMAT (64 * XS)         // 4352 floats
#define BMAT 4096              // B-format matrix (floats, 16KB)

__device__ __forceinline__ float f2tf_f(float f) {
    uint32_t u;
    asm("cvt.rna.tf32.f32 %0, %1;" : "=r"(u) : "f"(f));
    return __uint_as_float(u);
}
__device__ __forceinline__ uint32_t U(float f) { return __float_as_uint(f); }

__device__ __forceinline__ void mma_tf32(float d[4],
    float a0, float a1, float a2, float a3, float b0, float b1)
{
    asm volatile(
        "mma.sync.aligned.m16n8k8.row.col.f32.tf32.tf32.f32 "
        "{%0,%1,%2,%3}, {%4,%5,%6,%7}, {%8,%9}, {%0,%1,%2,%3};"
        : "+f"(d[0]), "+f"(d[1]), "+f"(d[2]), "+f"(d[3])
        : "r"(U(a0)), "r"(U(a1)), "r"(U(a2)), "r"(U(a3)), "r"(U(b0)), "r"(U(b1)));
}

__device__ __forceinline__ void zero_acc(float acc[8][4]) {
#pragma unroll
    for (int i = 0; i < 8; ++i)
#pragma unroll
        for (int j = 0; j < 4; ++j) acc[i][j] = 0.0f;
}

// B-format: logical B[k][n] (64x64) -> float offset.
// granule layout: [kt][lane=(n&7)*4+(k&3)][granule g4=(n>>3)>>1, XOR-swizzled]
// granule = {nt_even.b0, nt_even.b1, nt_odd.b0, nt_odd.b1}, pair = (k&7)>>2.
__device__ __forceinline__ int boff(int k, int n) {
    int kt = k >> 3, kk = k & 7;
    int lane_r = (n & 7) * 4 + (kk & 3);
    int nt = n >> 3;
    int g4 = nt >> 1;
    return kt * 512 + lane_r * 16 + ((g4 ^ ((lane_r >> 1) & 3)) << 2)
         + ((nt & 1) << 1) + (kk >> 2);
}

// acc(64x64 tile row-block) += x[m0..m0+15][0..63] @ B  (A from smem, B B-format)
__device__ __forceinline__ void gemm_xw(const float* __restrict__ xA,
                                        const float* __restrict__ Bs,
                                        float acc[8][4], int lane)
{
    const int g = lane >> 2, t = lane & 3;
    const int swz = (lane >> 1) & 3;
#pragma unroll
    for (int kt = 0; kt < 8; ++kt) {
        const float* ap = xA + g * XS + kt * 8 + t;
        float a0 = ap[0];            // A[r0][kt*8+t]
        float a1 = ap[8 * XS];       // A[r0+8][kt*8+t]
        float a2 = ap[4];            // A[r0][kt*8+t+4]
        float a3 = ap[8 * XS + 4];
        const float4* bp = (const float4*)(Bs + kt * 512 + lane * 16);
#pragma unroll
        for (int g4 = 0; g4 < 4; ++g4) {
            float4 b = bp[g4 ^ swz];
            mma_tf32(acc[2 * g4],     a0, a1, a2, a3, b.x, b.y);
            mma_tf32(acc[2 * g4 + 1], a0, a1, a2, a3, b.z, b.w);
        }
    }
}

// Convert one m16n8 accumulator tile (cols kt*8..+7) into the A-fragment for
// k-tile kt via intra-quad shuffles. src[0..3] = acc regs of that tile.
__device__ __forceinline__ void afrag_from_acc(const float src[4],
    int l0, int l1, bool hi, float& a0, float& a1, float& a2, float& a3)
{
    float s00 = __shfl_sync(0xffffffffu, src[0], l0);
    float s01 = __shfl_sync(0xffffffffu, src[1], l0);
    float s10 = __shfl_sync(0xffffffffu, src[0], l1);
    float s11 = __shfl_sync(0xffffffffu, src[1], l1);
    float s20 = __shfl_sync(0xffffffffu, src[2], l0);
    float s21 = __shfl_sync(0xffffffffu, src[3], l0);
    float s30 = __shfl_sync(0xffffffffu, src[2], l1);
    float s31 = __shfl_sync(0xffffffffu, src[3], l1);
    a0 = hi ? s01 : s00;   // row r0,   col kt*8+t
    a2 = hi ? s11 : s10;   // row r0,   col kt*8+t+4
    a1 = hi ? s21 : s20;   // row r0+8, col kt*8+t
    a3 = hi ? s31 : s30;   // row r0+8, col kt*8+t+4
}

__global__ void __launch_bounds__(THREADS, 1)
head_attn_kernel(const float* __restrict__ x,
                 const float* __restrict__ Wk,
                 const float* __restrict__ Wq,
                 const float* __restrict__ Wv,
                 float* __restrict__ out,
                 int nb)
{
    extern __shared__ float sm[];
    float* wq_b = sm;
    float* wk_b = sm + BMAT;
    float* wv_b = sm + 2 * BMAT;

    const int tid  = threadIdx.x;
    const int lane = tid & 31;
    const int warp = tid >> 5;
    const int slot = warp >> 2;       // batch within triple (0..2)
    const int w4   = warp & 3;        // row-block within batch
    const int g    = lane >> 2;
    const int t    = lane & 3;
    const int m0   = w4 * 16;
    const int r0   = m0 + g;
    const int swz  = (lane >> 1) & 3;
    const int lb   = lane & ~3;
    const int l0   = lb | (t >> 1);
    const int l1   = lb | ((t >> 1) + 2);
    const bool hi  = (t & 1) != 0;
    const int ntmax = 2 * w4 + 1;     // causal: last n-tile this warp needs

    float* xp = sm + 3 * BMAT + slot * (XMAT + 2 * BMAT);
    float* ks = xp + XMAT;            // K^T in B-format (k=h, n=s)
    float* vs = ks + BMAT;            // V   in B-format (k=s, n=h)

    // Weights -> B-format (tf32-rounded), once per CTA.
    for (int i = tid; i < 4096; i += THREADS) {
        int c = i >> 6, h = i & 63;
        int o = boff(c, h);
        wq_b[o] = f2tf_f(Wq[i]);
        wk_b[o] = f2tf_f(Wk[i]);
        wv_b[o] = f2tf_f(Wv[i]);
    }

    const int ntr = (nb + 2) / 3;
    for (int p = blockIdx.x; p < ntr; p += gridDim.x) {
        __syncthreads();  // previous iteration fully consumed smem

        // Stage x for 3 slots: coalesced LDG.128, STS.128, tf32-rounded.
        for (int i = tid; i < 3 * 1024; i += THREADS) {
            int s  = i >> 10;
            int j4 = i & 1023;
            int b  = 3 * p + s;
            if (b < nb) {
                float4 v = *(const float4*)(x + ((size_t)b << 12) + (j4 << 2));
                int r = j4 >> 4;
                int c = (j4 & 15) << 2;
                float* dst = sm + 3 * BMAT + s * (XMAT + 2 * BMAT) + r * XS + c;
                *(float4*)dst = make_float4(f2tf_f(v.x), f2tf_f(v.y),
                                            f2tf_f(v.z), f2tf_f(v.w));
            }
        }
        __syncthreads();

        const int b = 3 * p + slot;
        const float* xA = xp + m0 * XS;

        float tacc[8][4];

        // ---- K = x @ Wk, store transposed into B-format (k=h, n=s) ----
        zero_acc(tacc);
        gemm_xw(xA, wk_b, tacc, lane);
#pragma unroll
        for (int nt = 0; nt < 8; ++nt) {
            int h0 = nt * 8 + 2 * t;
            ks[boff(h0,     r0)]     = f2tf_f(tacc[nt][0]);
            ks[boff(h0 + 1, r0)]     = f2tf_f(tacc[nt][1]);
            ks[boff(h0,     r0 + 8)] = f2tf_f(tacc[nt][2]);
            ks[boff(h0 + 1, r0 + 8)] = f2tf_f(tacc[nt][3]);
        }

        // ---- V = x @ Wv, store into B-format (k=s, n=h) ----
        zero_acc(tacc);
        gemm_xw(xA, wv_b, tacc, lane);
#pragma unroll
        for (int nt = 0; nt < 8; ++nt) {
            int h0 = nt * 8 + 2 * t;
            vs[boff(r0,     h0)]     = f2tf_f(tacc[nt][0]);
            vs[boff(r0,     h0 + 1)] = f2tf_f(tacc[nt][1]);
            vs[boff(r0 + 8, h0)]     = f2tf_f(tacc[nt][2]);
            vs[boff(r0 + 8, h0 + 1)] = f2tf_f(tacc[nt][3]);
        }

        // ---- Q = x @ Wq: stays in registers ----
        float qacc[8][4];
        zero_acc(qacc);
        gemm_xw(xA, wq_b, qacc, lane);
        __syncthreads();  // K,V visible to all warps

        // ---- S = Q @ K^T (causal: n-tiles 0..ntmax only) ----
        float sacc[8][4];
        zero_acc(sacc);
#pragma unroll
        for (int kt = 0; kt < 8; ++kt) {
            float a0, a1, a2, a3;
            afrag_from_acc(qacc[kt], l0, l1, hi, a0, a1, a2, a3);
            a0 = f2tf_f(a0); a1 = f2tf_f(a1); a2 = f2tf_f(a2); a3 = f2tf_f(a3);
            const float4* bp = (const float4*)(ks + kt * 512 + lane * 16);
#pragma unroll
            for (int g4 = 0; g4 < 4; ++g4) {
                if (g4 > w4) break;
                float4 bb = bp[g4 ^ swz];
                mma_tf32(sacc[2 * g4],     a0, a1, a2, a3, bb.x, bb.y);
                mma_tf32(sacc[2 * g4 + 1], a0, a1, a2, a3, bb.z, bb.w);
            }
        }

        // ---- softmax (rows r0, r0+8), result tf32-rounded in sacc ----
        const float scale = 0.125f;  // C^-0.5
#pragma unroll
        for (int hh = 0; hh < 2; ++hh) {
            const int r  = r0 + hh * 8;
            const int i0 = 2 * hh;
            float mx = -1e30f;
#pragma unroll
            for (int nt = 0; nt < 8; ++nt) {
                if (nt > ntmax) break;
                int c = nt * 8 + 2 * t;
                float v0 = (c     <= r) ? sacc[nt][i0]     * scale : -1e30f;
                float v1 = (c + 1 <= r) ? sacc[nt][i0 + 1] * scale : -1e30f;
                sacc[nt][i0] = v0; sacc[nt][i0 + 1] = v1;
                mx = fmaxf(mx, fmaxf(v0, v1));
            }
            mx = fmaxf(mx, __shfl_xor_sync(0xffffffffu, mx, 1));
            mx = fmaxf(mx, __shfl_xor_sync(0xffffffffu, mx, 2));
            float ss = 0.0f;
#pragma unroll
            for (int nt = 0; nt < 8; ++nt) {
                if (nt > ntmax) break;
                float p0 = __expf(sacc[nt][i0]     - mx);
                float p1 = __expf(sacc[nt][i0 + 1] - mx);
                sacc[nt][i0] = p0; sacc[nt][i0 + 1] = p1;
                ss += p0 + p1;
            }
            ss += __shfl_xor_sync(0xffffffffu, ss, 1);
            ss += __shfl_xor_sync(0xffffffffu, ss, 2);
            const float inv = 1.0f / ss;
#pragma unroll
            for (int nt = 0; nt < 8; ++nt) {
                if (nt > ntmax) break;
                sacc[nt][i0]     = f2tf_f(sacc[nt][i0]     * inv);
                sacc[nt][i0 + 1] = f2tf_f(sacc[nt][i0 + 1] * inv);
            }
        }

        // ---- out = P @ V (causal: k-tiles 0..ntmax only) ----
        zero_acc(tacc);
#pragma unroll
        for (int kt = 0; kt < 8; ++kt) {
            if (kt > ntmax) break;
            float a0, a1, a2, a3;
            afrag_from_acc(sacc[kt], l0, l1, hi, a0, a1, a2, a3);
            const float4* bp = (const float4*)(vs + kt * 512 + lane * 16);
#pragma unroll
            for (int g4 = 0; g4 < 4; ++g4) {
                float4 bb = bp[g4 ^ swz];
                mma_tf32(tacc[2 * g4],     a0, a1, a2, a3, bb.x, bb.y);
                mma_tf32(tacc[2 * g4 + 1], a0, a1, a2, a3, bb.z, bb.w);
            }
        }

        if (b < nb) {
            float* ob = out + ((size_t)b << 12);
#pragma unroll
            for (int nt = 0; nt < 8; ++nt) {
                int c = nt * 8 + 2 * t;
                *(float2*)(ob + r0 * 64 + c) =
                    make_float2(tacc[nt][0], tacc[nt][1]);
                *(float2*)(ob + (r0 + 8) * 64 + c) =
                    make_float2(tacc[nt][2], tacc[nt][3]);
            }
        }
    }
}

extern "C" void kernel_launch(void* const* d_in, const int* in_sizes, int n_in,
                              void* d_out, int out_size)
{
    const float* x  = (const float*)d_in[0];
    const float* Wk = (const float*)d_in[1];
    const float* Wq = (const float*)d_in[2];
    const float* Wv = (const float*)d_in[3];
    float* out = (float*)d_out;
    const int nb = in_sizes[0] / (64 * 64);

    const size_t smem = (size_t)(3 * BMAT + 3 * (XMAT + 2 * BMAT)) * sizeof(float);
    cudaFuncSetAttribute(head_attn_kernel,
                         cudaFuncAttributeMaxDynamicSharedMemorySize, (int)smem);
    head_attn_kernel<<<GRID, THREADS, smem>>>(x, Wk, Wq, Wv, out, nb);
}

// round 7
// speedup vs baseline: 1.9376x; 1.4984x over previous
#include <cuda_runtime.h>
#include <cstdint>

// Head attention: B=16384, T=64, C=H=64, fp32.
// TF32 mma.sync m16n8k8. 3 batches/CTA (12 warps). K+V fused GEMM1 (one
// A-frag load feeds Wk and Wv), Q GEMM separate (reg-pressure safe).
// Column-permutation trick: Wq stored col-permuted and K stored seq-permuted
// so Q and P accumulators ARE the next GEMM's A fragments (zero shuffles).
// Next triple's x prefetched with cp.async into the dead xp buffer.

#define THREADS 384
#define GRID 148
#define XS 68                  // x row stride (floats)
#define XMAT (64 * XS)
#define BMAT 4096              // B-format matrix (floats, 16KB)

__device__ __forceinline__ float f2tf_f(float f) {
    uint32_t u;
    asm("cvt.rna.tf32.f32 %0, %1;" : "=r"(u) : "f"(f));
    return __uint_as_float(u);
}
__device__ __forceinline__ uint32_t U(float f) { return __float_as_uint(f); }

__device__ __forceinline__ void mma_tf32(float d[4],
    float a0, float a1, float a2, float a3, float b0, float b1)
{
    asm volatile(
        "mma.sync.aligned.m16n8k8.row.col.f32.tf32.tf32.f32 "
        "{%0,%1,%2,%3}, {%4,%5,%6,%7}, {%8,%9}, {%0,%1,%2,%3};"
        : "+f"(d[0]), "+f"(d[1]), "+f"(d[2]), "+f"(d[3])
        : "r"(U(a0)), "r"(U(a1)), "r"(U(a2)), "r"(U(a3)), "r"(U(b0)), "r"(U(b1)));
}

__device__ __forceinline__ void zero_acc(float acc[8][4]) {
#pragma unroll
    for (int i = 0; i < 8; ++i)
#pragma unroll
        for (int j = 0; j < 4; ++j) acc[i][j] = 0.0f;
}

// B-format: logical B[k][n] (64x64) -> float offset (XOR-swizzled granules).
__device__ __forceinline__ int boff(int k, int n) {
    int kt = k >> 3, kk = k & 7;
    int lane_r = (n & 7) * 4 + (kk & 3);
    int nt = n >> 3;
    int g4 = nt >> 1;
    return kt * 512 + lane_r * 16 + ((g4 ^ ((lane_r >> 1) & 3)) << 2)
         + ((nt & 1) << 1) + (kk >> 2);
}

// pi(j): within-8 permutation (j<4 -> 2j, else 2(j-4)+1)
__device__ __forceinline__ int perm8(int j) {
    return (j & 4) ? (((j & 3) << 1) | 1) : (j << 1);
}

__device__ __forceinline__ void cp16(float* dst_smem, const float* src) {
    uint32_t d = (uint32_t)__cvta_generic_to_shared(dst_smem);
    asm volatile("cp.async.cg.shared.global [%0], [%1], 16;" :: "r"(d), "l"(src));
}

__global__ void __launch_bounds__(THREADS, 1)
head_attn_kernel(const float* __restrict__ x,
                 const float* __restrict__ Wk,
                 const float* __restrict__ Wq,
                 const float* __restrict__ Wv,
                 float* __restrict__ out,
                 int nb)
{
    extern __shared__ float sm[];
    float* wq_b = sm;                 // col-permuted (pi on h)
    float* wk_b = sm + BMAT;
    float* wv_b = sm + 2 * BMAT;

    const int tid  = threadIdx.x;
    const int lane = tid & 31;
    const int warp = tid >> 5;
    const int slot = warp >> 2;       // batch within triple
    const int w4   = warp & 3;        // 16-row block
    const int g    = lane >> 2;
    const int t    = lane & 3;
    const int m0   = w4 * 16;
    const int r0   = m0 + g;
    const int swz  = (lane >> 1) & 3;
    const int ntmax = 2 * w4 + 1;
    const int sr0  = m0 + perm8(g);   // sigma(r0): K-row store position
    const int sr8  = sr0 + 8;

    float* xp = sm + 3 * BMAT + slot * (XMAT + 2 * BMAT);
    float* ks = xp + XMAT;            // K^T B-format (k=h, n=sigma(s))
    float* vs = ks + BMAT;            // V   B-format (k=s, n=h)
    float* xall = sm + 3 * BMAT;

    // Weights -> B-format once per CTA (Wq column-permuted).
    for (int i = tid; i < 4096; i += THREADS) {
        int c = i >> 6, h = i & 63;
        wq_b[boff(c, (h & ~7) | perm8(h & 7))] = f2tf_f(Wq[i]);
        wk_b[boff(c, h)] = f2tf_f(Wk[i]);
        wv_b[boff(c, h)] = f2tf_f(Wv[i]);
    }

    const int ntr = (nb + 2) / 3;

    // Prologue prefetch of the first triple.
    {
        int p = blockIdx.x;
        for (int i = tid; i < 3072; i += THREADS) {
            int s = i >> 10, j4 = i & 1023;
            int b = 3 * p + s;
            if (b < nb)
                cp16(xall + s * (XMAT + 2 * BMAT) + (j4 >> 4) * XS + (j4 & 15) * 4,
                     x + ((size_t)b << 12) + (j4 << 2));
        }
        asm volatile("cp.async.commit_group;");
    }

    for (int p = blockIdx.x; p < ntr; p += gridDim.x) {
        asm volatile("cp.async.wait_group 0;" ::: "memory");
        __syncthreads();   // x ready; prior iter's ks/vs consumers done

        const int b = 3 * p + slot;
        const float* xA = xp + m0 * XS;

        // ---- GEMM1a: K and V from one A-fragment stream ----
        float kacc[8][4], vacc[8][4];
        zero_acc(kacc); zero_acc(vacc);
#pragma unroll
        for (int kt = 0; kt < 8; ++kt) {
            const float* ap = xA + g * XS + kt * 8 + t;
            float a0 = f2tf_f(ap[0]);
            float a1 = f2tf_f(ap[8 * XS]);
            float a2 = f2tf_f(ap[4]);
            float a3 = f2tf_f(ap[8 * XS + 4]);
            const float4* bk = (const float4*)(wk_b + kt * 512 + lane * 16);
            const float4* bv = (const float4*)(wv_b + kt * 512 + lane * 16);
#pragma unroll
            for (int g4 = 0; g4 < 4; ++g4) {
                float4 k = bk[g4 ^ swz];
                mma_tf32(kacc[2 * g4],     a0, a1, a2, a3, k.x, k.y);
                mma_tf32(kacc[2 * g4 + 1], a0, a1, a2, a3, k.z, k.w);
                float4 v = bv[g4 ^ swz];
                mma_tf32(vacc[2 * g4],     a0, a1, a2, a3, v.x, v.y);
                mma_tf32(vacc[2 * g4 + 1], a0, a1, a2, a3, v.z, v.w);
            }
        }
        // K store: transposed B-format, sequence position sigma(r).
#pragma unroll
        for (int nt = 0; nt < 8; ++nt) {
            int h0 = nt * 8 + 2 * t;
            ks[boff(h0,     sr0)] = f2tf_f(kacc[nt][0]);
            ks[boff(h0 + 1, sr0)] = f2tf_f(kacc[nt][1]);
            ks[boff(h0,     sr8)] = f2tf_f(kacc[nt][2]);
            ks[boff(h0 + 1, sr8)] = f2tf_f(kacc[nt][3]);
        }
        // V store: B-format (k=s identity, n=h identity).
#pragma unroll
        for (int nt = 0; nt < 8; ++nt) {
            int h0 = nt * 8 + 2 * t;
            vs[boff(r0,     h0)]     = f2tf_f(vacc[nt][0]);
            vs[boff(r0,     h0 + 1)] = f2tf_f(vacc[nt][1]);
            vs[boff(r0 + 8, h0)]     = f2tf_f(vacc[nt][2]);
            vs[boff(r0 + 8, h0 + 1)] = f2tf_f(vacc[nt][3]);
        }

        // ---- GEMM1b: Q (accumulator IS the S-GEMM A-fragment) ----
        float qacc[8][4];
        zero_acc(qacc);
#pragma unroll
        for (int kt = 0; kt < 8; ++kt) {
            const float* ap = xA + g * XS + kt * 8 + t;
            float a0 = f2tf_f(ap[0]);
            float a1 = f2tf_f(ap[8 * XS]);
            float a2 = f2tf_f(ap[4]);
            float a3 = f2tf_f(ap[8 * XS + 4]);
            const float4* bq = (const float4*)(wq_b + kt * 512 + lane * 16);
#pragma unroll
            for (int g4 = 0; g4 < 4; ++g4) {
                float4 q = bq[g4 ^ swz];
                mma_tf32(qacc[2 * g4],     a0, a1, a2, a3, q.x, q.y);
                mma_tf32(qacc[2 * g4 + 1], a0, a1, a2, a3, q.z, q.w);
            }
        }
        __syncthreads();   // ks/vs visible; xp now dead

        // ---- prefetch next triple's x into xp (hidden behind S/PV) ----
        {
            int pn = p + gridDim.x;
            if (pn < ntr) {
                for (int i = tid; i < 3072; i += THREADS) {
                    int s = i >> 10, j4 = i & 1023;
                    int bn = 3 * pn + s;
                    if (bn < nb)
                        cp16(xall + s * (XMAT + 2 * BMAT) + (j4 >> 4) * XS + (j4 & 15) * 4,
                             x + ((size_t)bn << 12) + (j4 << 2));
                }
            }
            asm volatile("cp.async.commit_group;");
        }

        // ---- S = Q @ K^T (qacc IS the A-fragment; causal tiles only) ----
        float sacc[8][4];
        zero_acc(sacc);
#pragma unroll
        for (int kt = 0; kt < 8; ++kt) {
            float a0 = f2tf_f(qacc[kt][0]);   // row r0,   h=kt*8+t
            float a1 = f2tf_f(qacc[kt][2]);   // row r0+8, h=kt*8+t
            float a2 = f2tf_f(qacc[kt][1]);   // row r0,   h=kt*8+t+4
            float a3 = f2tf_f(qacc[kt][3]);   // row r0+8, h=kt*8+t+4
            const float4* bp = (const float4*)(ks + kt * 512 + lane * 16);
#pragma unroll
            for (int g4 = 0; g4 < 4; ++g4) {
                if (g4 > w4) break;
                float4 bb = bp[g4 ^ swz];
                mma_tf32(sacc[2 * g4],     a0, a1, a2, a3, bb.x, bb.y);
                mma_tf32(sacc[2 * g4 + 1], a0, a1, a2, a3, bb.z, bb.w);
            }
        }

        // ---- softmax; entry [nt][0] is s=nt*8+t, [nt][1] is s=nt*8+t+4 ----
        const float scale = 0.125f;  // C^-0.5
#pragma unroll
        for (int hh = 0; hh < 2; ++hh) {
            const int r  = r0 + hh * 8;
            const int i0 = 2 * hh;
            float mx = -1e30f;
#pragma unroll
            for (int nt = 0; nt < 8; ++nt) {
                if (nt > ntmax) break;
                int s0 = nt * 8 + t;
                float v0 = (s0     <= r) ? sacc[nt][i0]     * scale : -1e30f;
                float v1 = (s0 + 4 <= r) ? sacc[nt][i0 + 1] * scale : -1e30f;
                sacc[nt][i0] = v0; sacc[nt][i0 + 1] = v1;
                mx = fmaxf(mx, fmaxf(v0, v1));
            }
            mx = fmaxf(mx, __shfl_xor_sync(0xffffffffu, mx, 1));
            mx = fmaxf(mx, __shfl_xor_sync(0xffffffffu, mx, 2));
            float ss = 0.0f;
#pragma unroll
            for (int nt = 0; nt < 8; ++nt) {
                if (nt > ntmax) break;
                float p0 = __expf(sacc[nt][i0]     - mx);
                float p1 = __expf(sacc[nt][i0 + 1] - mx);
                sacc[nt][i0] = p0; sacc[nt][i0 + 1] = p1;
                ss += p0 + p1;
            }
            ss += __shfl_xor_sync(0xffffffffu, ss, 1);
            ss += __shfl_xor_sync(0xffffffffu, ss, 2);
            const float inv = 1.0f / ss;
#pragma unroll
            for (int nt = 0; nt < 8; ++nt) {
                if (nt > ntmax) break;
                sacc[nt][i0]     = f2tf_f(sacc[nt][i0]     * inv);
                sacc[nt][i0 + 1] = f2tf_f(sacc[nt][i0 + 1] * inv);
            }
        }

        // ---- out = P @ V (sacc IS the A-fragment; causal k-tiles) ----
        float tacc[8][4];
        zero_acc(tacc);
#pragma unroll
        for (int kt = 0; kt < 8; ++kt) {
            if (kt > ntmax) break;
            float a0 = sacc[kt][0];   // row r0,   s=kt*8+t
            float a1 = sacc[kt][2];   // row r0+8, s=kt*8+t
            float a2 = sacc[kt][1];   // row r0,   s=kt*8+t+4
            float a3 = sacc[kt][3];   // row r0+8, s=kt*8+t+4
            const float4* bp = (const float4*)(vs + kt * 512 + lane * 16);
#pragma unroll
            for (int g4 = 0; g4 < 4; ++g4) {
                float4 bb = bp[g4 ^ swz];
                mma_tf32(tacc[2 * g4],     a0, a1, a2, a3, bb.x, bb.y);
                mma_tf32(tacc[2 * g4 + 1], a0, a1, a2, a3, bb.z, bb.w);
            }
        }

        if (b < nb) {
            float* ob = out + ((size_t)b << 12);
#pragma unroll
            for (int nt = 0; nt < 8; ++nt) {
                int c = nt * 8 + 2 * t;
                *(float2*)(ob + r0 * 64 + c) =
                    make_float2(tacc[nt][0], tacc[nt][1]);
                *(float2*)(ob + (r0 + 8) * 64 + c) =
                    make_float2(tacc[nt][2], tacc[nt][3]);
            }
        }
    }
}

extern "C" void kernel_launch(void* const* d_in, const int* in_sizes, int n_in,
                              void* d_out, int out_size)
{
    const float* x  = (const float*)d_in[0];
    const float* Wk = (const float*)d_in[1];
    const float* Wq = (const float*)d_in[2];
    const float* Wv = (const float*)d_in[3];
    float* out = (float*)d_out;
    const int nb = in_sizes[0] / (64 * 64);

    const size_t smem = (size_t)(3 * BMAT + 3 * (XMAT + 2 * BMAT)) * sizeof(float);
    cudaFuncSetAttribute(head_attn_kernel,
                         cudaFuncAttributeMaxDynamicSharedMemorySize, (int)smem);
    head_attn_kernel<<<GRID, THREADS, smem>>>(x, Wk, Wq, Wv, out, nb);
}